// round 3
// baseline (speedup 1.0000x reference)
#include <cuda_runtime.h>

#define NN   25000
#define EE   400000
#define FIN  256
#define CC   32
#define AA   9
#define WN   288     // CC*AA
#define BB   8
#define HH   64
#define SSP  4
#define FOUT 256

__device__ float g_h[NN * CC];      // 3.2 MB
__device__ float g_agg[NN * WN];    // 28.8 MB

__device__ __forceinline__ float silu_f(float v) {
    return v / (1.0f + __expf(-v));
}

// ---- packed f32x2 helpers ----
__device__ __forceinline__ void fma2(unsigned long long& acc, unsigned long long a,
                                     unsigned long long b) {
    asm("fma.rn.f32x2 %0, %1, %2, %0;" : "+l"(acc) : "l"(a), "l"(b));
}
__device__ __forceinline__ unsigned long long pack2(float x, float y) {
    unsigned long long r;
    asm("mov.b64 %0, {%1, %2};" : "=l"(r) : "f"(x), "f"(y));
    return r;
}
__device__ __forceinline__ float2 unpack2(unsigned long long v) {
    float2 r;
    asm("mov.b64 {%0, %1}, %2;" : "=f"(r.x), "=f"(r.y) : "l"(v));
    return r;
}
__device__ __forceinline__ unsigned long long lds64(const float* p) {
    return *reinterpret_cast<const unsigned long long*>(p);
}

// ---------------------------------------------------------------------------
__global__ void k_zero() {
    int i = blockIdx.x * blockDim.x + threadIdx.x;
    int stride = gridDim.x * blockDim.x;
    float4* p = (float4*)g_agg;
    const int n4 = (NN * WN) / 4;
    float4 z = make_float4(0.f, 0.f, 0.f, 0.f);
    for (; i < n4; i += stride) p[i] = z;
}

// ---------------------------------------------------------------------------
// h = 0.25 * (x @ W1)    [NN, CC]
// ---------------------------------------------------------------------------
__global__ void __launch_bounds__(256) k_h(const float* __restrict__ x,
                                           const float* __restrict__ W1) {
    __shared__ float sW1[FIN * CC];
    __shared__ float sX[8][FIN];
    int t = threadIdx.x;
    int n0 = blockIdx.x * 8;
    for (int i = t; i < FIN * CC; i += 256) sW1[i] = W1[i];
    for (int i = t; i < 8 * FIN; i += 256)
        sX[i >> 8][i & 255] = x[(n0 + (i >> 8)) * FIN + (i & 255)];
    __syncthreads();
    int ty = t >> 5, tx = t & 31;
    float acc = 0.f;
#pragma unroll 8
    for (int f = 0; f < FIN; f++) acc += sX[ty][f] * sW1[f * CC + tx];
    g_h[(n0 + ty) * CC + tx] = 0.25f * acc;
}

// ---------------------------------------------------------------------------
// sc_out GEMM: out[n,o] = sum_k xa[n,k]*Wsc[k,o], K=1024
// tile 64x128, block 256, micro 4x8, k-pair FFMA2 (no packing movs)
// ---------------------------------------------------------------------------
__global__ void __launch_bounds__(256) k_sc(const float* __restrict__ x,
                                            const float* __restrict__ attrs,
                                            const float* __restrict__ Wsc,
                                            float* __restrict__ out) {
    __shared__ unsigned long long sAp[16 * 64];    // [kp][n] pairs (k,k+1)
    __shared__ unsigned long long sBp[16 * 128];   // [kp][o] pairs
    int t = threadIdx.x;
    int n0 = blockIdx.x * 64;
    int o0 = blockIdx.y * 128;
    int tr = t & 15;   // n = tr + 16i
    int tc = t >> 4;   // o = tc + 16j
    unsigned long long acc2[4][8];
#pragma unroll
    for (int i = 0; i < 4; i++)
#pragma unroll
        for (int j = 0; j < 8; j++) acc2[i][j] = 0ull;

    for (int kc = 0; kc < FIN * SSP; kc += 32) {
        // A pairs
        for (int i = t; i < 16 * 64; i += 256) {
            int kp = i >> 6, n = i & 63;
            int k0 = kc + 2 * kp;
            int nn = n0 + n;
            float a0 = 0.f, a1 = 0.f;
            if (nn < NN) {
                a0 = x[nn * FIN + (k0 >> 2)] * attrs[nn * SSP + (k0 & 3)];
                a1 = x[nn * FIN + ((k0 + 1) >> 2)] * attrs[nn * SSP + ((k0 + 1) & 3)];
            }
            sAp[i] = pack2(a0, a1);
        }
        // B pairs
        for (int i = t; i < 16 * 128; i += 256) {
            int kp = i >> 7, o = i & 127;
            int k0 = kc + 2 * kp;
            sBp[i] = pack2(Wsc[k0 * FOUT + o0 + o], Wsc[(k0 + 1) * FOUT + o0 + o]);
        }
        __syncthreads();
#pragma unroll 4
        for (int kp = 0; kp < 16; kp++) {
            unsigned long long a2[4], b2[8];
#pragma unroll
            for (int i = 0; i < 4; i++) a2[i] = sAp[kp * 64 + tr + 16 * i];
#pragma unroll
            for (int j = 0; j < 8; j++) b2[j] = sBp[kp * 128 + tc + 16 * j];
#pragma unroll
            for (int i = 0; i < 4; i++)
#pragma unroll
                for (int j = 0; j < 8; j++) fma2(acc2[i][j], a2[i], b2[j]);
        }
        __syncthreads();
    }
#pragma unroll
    for (int i = 0; i < 4; i++) {
        int nn = n0 + tr + 16 * i;
        if (nn >= NN) continue;
#pragma unroll
        for (int j = 0; j < 8; j++) {
            float2 r = unpack2(acc2[i][j]);
            out[nn * FOUT + o0 + tc + 16 * j] = r.x + r.y;
        }
    }
}

// ---------------------------------------------------------------------------
// fused edge kernel
// ---------------------------------------------------------------------------
#define ACTP 65   // sAct row stride (odd -> conflict-free scalar reads)
#define TSTR 66   // sActT row stride (even -> aligned lds64)

__global__ void __launch_bounds__(256, 1) k_edge(
    const float* __restrict__ eeG, const float* __restrict__ shG,
    const int* __restrict__ dstG, const int* __restrict__ srcG,
    const float* __restrict__ Wm1, const float* __restrict__ Wm2,
    const float* __restrict__ Wm3) {
    extern __shared__ float sm[];
    float* sWm1  = sm;                     // 512
    float* sWm2  = sWm1 + 512;             // 4096
    float* sWm3  = sWm2 + 4096;            // 18432
    float* sAct  = sWm3 + 18432;           // 64*65 = 4160  (h1, e-major)
    float* sActT = sAct + 64 * ACTP;       // 64*66 = 4224  (h2, k-major)
    float* sEE   = sActT + 64 * TSTR;      // 512
    float* sSH   = sEE + 512;              // 576
    float* sHs   = sSH + 576;              // 2048
    int*   sDst  = (int*)(sHs + 2048);     // 64
    int*   sSrc  = sDst + 64;              // 64

    int t = threadIdx.x;
    for (int i = t; i < 512;   i += 256) sWm1[i] = Wm1[i];
    for (int i = t; i < 4096;  i += 256) sWm2[i] = Wm2[i];
    for (int i = t; i < 18432; i += 256) sWm3[i] = Wm3[i];
    __syncthreads();

    const int tx = t & 31, ty = t >> 5;
    const int e_loc = t & 63;
    const int j0 = (t >> 6) * 16;

    // per-thread (c,a) decomposition for outs o = tx + 32j
    int cj[9], aj[9];
#pragma unroll
    for (int j = 0; j < 9; j++) {
        int o = tx + 32 * j;
        cj[j] = o / 9;
        aj[j] = o - 9 * cj[j];
    }

    for (int tile = blockIdx.x; tile < EE / 64; tile += gridDim.x) {
        int e0g = tile * 64;
        for (int i = t; i < 64 * BB; i += 256) sEE[i] = eeG[e0g * BB + i];
        for (int i = t; i < 64 * AA; i += 256) sSH[i] = shG[e0g * AA + i];
        if (t < 64) { sDst[t] = dstG[e0g + t]; sSrc[t] = srcG[e0g + t]; }
        __syncthreads();

        for (int i = t; i < 64 * CC; i += 256) {
            int e = i >> 5, c = i & 31;
            sHs[i] = g_h[sSrc[e] * CC + c];
        }

        // phase 1: h1 = silu(ee @ Wm1)
        {
            float acc[16];
#pragma unroll
            for (int j = 0; j < 16; j++) acc[j] = 0.f;
#pragma unroll
            for (int b = 0; b < BB; b++) {
                float v = sEE[e_loc * BB + b];
#pragma unroll
                for (int j = 0; j < 16; j++) acc[j] += v * sWm1[b * HH + j0 + j];
            }
#pragma unroll
            for (int j = 0; j < 16; j++) sAct[e_loc * ACTP + j0 + j] = silu_f(acc[j]);
        }
        __syncthreads();

        // phase 2: h2 = silu(h1 @ Wm2), write TRANSPOSED into sActT[k][e]
        {
            float acc[16];
#pragma unroll
            for (int j = 0; j < 16; j++) acc[j] = 0.f;
#pragma unroll 8
            for (int k = 0; k < HH; k++) {
                float v = sAct[e_loc * ACTP + k];
#pragma unroll
                for (int j = 0; j < 16; j++) acc[j] += v * sWm2[k * HH + j0 + j];
            }
#pragma unroll
            for (int j = 0; j < 16; j++)
                sActT[(j0 + j) * TSTR + e_loc] = silu_f(acc[j]);
        }
        __syncthreads();

        // phase 3: edge-pair FFMA2 GEMM + TP epilogue + scatter
        // thread: 4 edge-pairs (ep = ty + 8i) x 9 outs (o = tx + 32j)
        {
            unsigned long long acc2[4][9];
#pragma unroll
            for (int i = 0; i < 4; i++)
#pragma unroll
                for (int j = 0; j < 9; j++) acc2[i][j] = 0ull;

#pragma unroll 2
            for (int k = 0; k < HH; k++) {
                unsigned long long a2[4];
#pragma unroll
                for (int i = 0; i < 4; i++)
                    a2[i] = lds64(&sActT[k * TSTR + 2 * (ty + 8 * i)]);  // broadcast
                unsigned long long bb[9];
#pragma unroll
                for (int j = 0; j < 9; j++) {
                    float b = sWm3[k * WN + tx + 32 * j];
                    bb[j] = pack2(b, b);
                }
#pragma unroll
                for (int i = 0; i < 4; i++)
#pragma unroll
                    for (int j = 0; j < 9; j++) fma2(acc2[i][j], a2[i], bb[j]);
            }

            // epilogue: lanes = 2 edges; msg = w * h[src,c] * sh[a]; scatter
#pragma unroll
            for (int i = 0; i < 4; i++) {
                int e0 = 2 * (ty + 8 * i);
                int e1 = e0 + 1;
                float* d0 = g_agg + (long long)sDst[e0] * WN;
                float* d1 = g_agg + (long long)sDst[e1] * WN;
                const float* hs0 = &sHs[e0 * CC];
                const float* hs1 = &sHs[e1 * CC];
                const float* sh0 = &sSH[e0 * AA];
                const float* sh1 = &sSH[e1 * AA];
#pragma unroll
                for (int j = 0; j < 9; j++) {
                    int o = tx + 32 * j;
                    float2 w = unpack2(acc2[i][j]);
                    atomicAdd(d0 + o, w.x * hs0[cj[j]] * sh0[aj[j]]);
                    atomicAdd(d1 + o, w.y * hs1[cj[j]] * sh1[aj[j]]);
                }
            }
        }
        __syncthreads();
    }
}

// ---------------------------------------------------------------------------
// out = silu(agg @ W2) + sc_out, tile 64x64, micro 4x4, k-pair FFMA2, K=288
// ---------------------------------------------------------------------------
__global__ void __launch_bounds__(256) k_final(const float* __restrict__ W2,
                                               float* __restrict__ out) {
    __shared__ unsigned long long sAp[16 * 64];   // [kp][n]
    __shared__ unsigned long long sBp[16 * 64];   // [kp][o]
    int t = threadIdx.x;
    int n0 = blockIdx.x * 64;
    int o0 = blockIdx.y * 64;
    int tr = t & 15, tc = t >> 4;
    unsigned long long acc2[4][4];
#pragma unroll
    for (int i = 0; i < 4; i++)
#pragma unroll
        for (int j = 0; j < 4; j++) acc2[i][j] = 0ull;

    for (int kc = 0; kc < WN; kc += 32) {
        for (int i = t; i < 16 * 64; i += 256) {
            int n = i >> 4, kp = i & 15;
            int nn = n0 + n;
            unsigned long long v = 0ull;
            if (nn < NN)
                v = *(const unsigned long long*)&g_agg[(long long)nn * WN + kc + 2 * kp];
            sAp[kp * 64 + n] = v;
        }
        for (int i = t; i < 16 * 64; i += 256) {
            int kp = i >> 6, o = i & 63;
            int k0 = kc + 2 * kp;
            sBp[i] = pack2(W2[k0 * FOUT + o0 + o], W2[(k0 + 1) * FOUT + o0 + o]);
        }
        __syncthreads();
#pragma unroll 4
        for (int kp = 0; kp < 16; kp++) {
            unsigned long long a2[4], b2[4];
#pragma unroll
            for (int i = 0; i < 4; i++) a2[i] = sAp[kp * 64 + tr + 16 * i];
#pragma unroll
            for (int j = 0; j < 4; j++) b2[j] = sBp[kp * 64 + tc + 16 * j];
#pragma unroll
            for (int i = 0; i < 4; i++)
#pragma unroll
                for (int j = 0; j < 4; j++) fma2(acc2[i][j], a2[i], b2[j]);
        }
        __syncthreads();
    }
#pragma unroll
    for (int i = 0; i < 4; i++) {
        int nn = n0 + tr + 16 * i;
        if (nn >= NN) continue;
#pragma unroll
        for (int j = 0; j < 4; j++) {
            int o = o0 + tc + 16 * j;
            float2 r = unpack2(acc2[i][j]);
            out[nn * FOUT + o] = silu_f(r.x + r.y) + out[nn * FOUT + o];
        }
    }
}

// ---------------------------------------------------------------------------
extern "C" void kernel_launch(void* const* d_in, const int* in_sizes, int n_in,
                              void* d_out, int out_size) {
    const float* x     = (const float*)d_in[0];
    const float* attrs = (const float*)d_in[1];
    const float* ee    = (const float*)d_in[2];
    const float* sh    = (const float*)d_in[3];
    const int*   eidx  = (const int*)d_in[4];
    const float* W1    = (const float*)d_in[5];
    const float* Wm1   = (const float*)d_in[6];
    const float* Wm2   = (const float*)d_in[7];
    const float* Wm3   = (const float*)d_in[8];
    const float* W2    = (const float*)d_in[9];
    const float* Wsc   = (const float*)d_in[10];
    float* out = (float*)d_out;

    const int* dst = eidx;        // edge_index[0]
    const int* src = eidx + EE;   // edge_index[1]

    k_zero<<<1024, 256>>>();
    k_h<<<NN / 8, 256>>>(x, W1);

    dim3 gsc((NN + 63) / 64, 2);
    k_sc<<<gsc, 256>>>(x, attrs, Wsc, out);

    const int edge_smem =
        (512 + 4096 + 18432 + 64 * ACTP + 64 * TSTR + 512 + 576 + 2048) * 4 + 128 * 4;
    cudaFuncSetAttribute(k_edge, cudaFuncAttributeMaxDynamicSharedMemorySize, edge_smem);
    k_edge<<<152, 256, edge_smem>>>(ee, sh, dst, src, Wm1, Wm2, Wm3);

    dim3 gf((NN + 63) / 64, 4);
    k_final<<<gf, 256>>>(W2, out);
}

// round 5
// speedup vs baseline: 1.0900x; 1.0900x over previous
#include <cuda_runtime.h>

#define NN   25000
#define EE   400000
#define FIN  256
#define CC   32
#define AA   9
#define WN   288     // CC*AA
#define BB   8
#define HH   64
#define SSP  4
#define FOUT 256

__device__ float g_h[NN * CC];      // 3.2 MB
__device__ float g_agg[NN * WN];    // 28.8 MB

__device__ __forceinline__ float silu_f(float v) {
    return v / (1.0f + __expf(-v));
}

// ---- packed f32x2 helpers ----
__device__ __forceinline__ void fma2(unsigned long long& acc, unsigned long long a,
                                     unsigned long long b) {
    asm("fma.rn.f32x2 %0, %1, %2, %0;" : "+l"(acc) : "l"(a), "l"(b));
}
__device__ __forceinline__ unsigned long long pack2(float x, float y) {
    unsigned long long r;
    asm("mov.b64 %0, {%1, %2};" : "=l"(r) : "f"(x), "f"(y));
    return r;
}
__device__ __forceinline__ float2 unpack2(unsigned long long v) {
    float2 r;
    asm("mov.b64 {%0, %1}, %2;" : "=f"(r.x), "=f"(r.y) : "l"(v));
    return r;
}
__device__ __forceinline__ unsigned long long lds64(const float* p) {
    return *reinterpret_cast<const unsigned long long*>(p);
}

// ---------------------------------------------------------------------------
__global__ void k_zero() {
    int i = blockIdx.x * blockDim.x + threadIdx.x;
    int stride = gridDim.x * blockDim.x;
    float4* p = (float4*)g_agg;
    const int n4 = (NN * WN) / 4;
    float4 z = make_float4(0.f, 0.f, 0.f, 0.f);
    for (; i < n4; i += stride) p[i] = z;
}

// ---------------------------------------------------------------------------
// h = 0.25 * (x @ W1)    [NN, CC]
// ---------------------------------------------------------------------------
__global__ void __launch_bounds__(256) k_h(const float* __restrict__ x,
                                           const float* __restrict__ W1) {
    __shared__ float sW1[FIN * CC];
    __shared__ float sX[8][FIN];
    int t = threadIdx.x;
    int n0 = blockIdx.x * 8;
    for (int i = t; i < FIN * CC; i += 256) sW1[i] = W1[i];
    for (int i = t; i < 8 * FIN; i += 256)
        sX[i >> 8][i & 255] = x[(n0 + (i >> 8)) * FIN + (i & 255)];
    __syncthreads();
    int ty = t >> 5, tx = t & 31;
    float acc = 0.f;
#pragma unroll 8
    for (int f = 0; f < FIN; f++) acc += sX[ty][f] * sW1[f * CC + tx];
    g_h[(n0 + ty) * CC + tx] = 0.25f * acc;
}

// ---------------------------------------------------------------------------
// sc_out GEMM (R1 scalar version): tile 64x128, micro 4x8
// ---------------------------------------------------------------------------
__global__ void __launch_bounds__(256) k_sc(const float* __restrict__ x,
                                            const float* __restrict__ attrs,
                                            const float* __restrict__ Wsc,
                                            float* __restrict__ out) {
    __shared__ float sA[32][64];
    __shared__ float sB[32][128];
    int t = threadIdx.x;
    int n0 = blockIdx.x * 64;
    int o0 = blockIdx.y * 128;
    int tr = t >> 4;
    int tc = t & 15;
    float acc[4][8];
#pragma unroll
    for (int i = 0; i < 4; i++)
#pragma unroll
        for (int j = 0; j < 8; j++) acc[i][j] = 0.f;

    for (int kc = 0; kc < FIN * SSP; kc += 32) {
        for (int i = t; i < 32 * 64; i += 256) {
            int kk = i >> 6, n = i & 63;
            int k = kc + kk;
            int nn = n0 + n;
            float v = 0.f;
            if (nn < NN) v = x[nn * FIN + (k >> 2)] * attrs[nn * SSP + (k & 3)];
            sA[kk][n] = v;
        }
        for (int i = t; i < 32 * 128; i += 256) {
            int kk = i >> 7, o = i & 127;
            sB[kk][o] = Wsc[(kc + kk) * FOUT + o0 + o];
        }
        __syncthreads();
#pragma unroll 8
        for (int k = 0; k < 32; k++) {
            float a[4], b[8];
#pragma unroll
            for (int i = 0; i < 4; i++) a[i] = sA[k][tr * 4 + i];
#pragma unroll
            for (int j = 0; j < 8; j++) b[j] = sB[k][tc * 8 + j];
#pragma unroll
            for (int i = 0; i < 4; i++)
#pragma unroll
                for (int j = 0; j < 8; j++) acc[i][j] += a[i] * b[j];
        }
        __syncthreads();
    }
#pragma unroll
    for (int i = 0; i < 4; i++) {
        int nn = n0 + tr * 4 + i;
        if (nn >= NN) continue;
#pragma unroll
        for (int j = 0; j < 8; j++)
            out[nn * FOUT + o0 + tc * 8 + j] = acc[i][j];
    }
}

// ---------------------------------------------------------------------------
// fused edge kernel: 512 threads, 128-edge tiles, edge-pair FFMA2 phase 3
// ---------------------------------------------------------------------------
#define ETILE 128
#define NTILE (EE / ETILE)   // 3125
#define ACTP  65             // sAct row stride (odd -> conflict-free reads)
#define TSTR  130            // sActT row stride: >=ETILE, even for aligned lds64

__global__ void __launch_bounds__(512, 1) k_edge(
    const float* __restrict__ eeG, const float* __restrict__ shG,
    const int* __restrict__ dstG, const int* __restrict__ srcG,
    const float* __restrict__ Wm1, const float* __restrict__ Wm2,
    const float* __restrict__ Wm3) {
    extern __shared__ float sm[];
    float* sWm1  = sm;                       // 512
    float* sWm2  = sWm1 + 512;               // 4096
    float* sWm3  = sWm2 + 4096;              // 18432
    float* sAct  = sWm3 + 18432;             // 128*65 = 8320
    float* sActT = sAct + ETILE * ACTP;      // 64*130 = 8320... (HH rows)
    float* sEE   = sActT + HH * TSTR;        // 1024
    float* sSH   = sEE + ETILE * BB;         // 1152
    float* sHs   = sSH + ETILE * AA;         // 4096
    int*   sDst  = (int*)(sHs + ETILE * CC); // 128
    int*   sSrc  = sDst + ETILE;             // 128

    int t = threadIdx.x;
    for (int i = t; i < 512;   i += 512) sWm1[i] = Wm1[i];
    for (int i = t; i < 4096;  i += 512) sWm2[i] = Wm2[i];
    for (int i = t; i < 18432; i += 512) sWm3[i] = Wm3[i];
    __syncthreads();

    const int tx = t & 31;
    const int wp = t >> 5;          // warp id 0..15
    const int e2 = t >> 2;          // phase 1/2 edge 0..127
    const int j02 = (t & 3) * 16;   // phase 1/2 out group

    int cj[9], aj[9];
#pragma unroll
    for (int j = 0; j < 9; j++) {
        int o = tx + 32 * j;
        cj[j] = o / 9;
        aj[j] = o - 9 * cj[j];
    }

    for (int tile = blockIdx.x; tile < NTILE; tile += gridDim.x) {
        int e0g = tile * ETILE;
        for (int i = t; i < ETILE * BB; i += 512) sEE[i] = eeG[e0g * BB + i];
        for (int i = t; i < ETILE * AA; i += 512) sSH[i] = shG[e0g * AA + i];
        if (t < ETILE) { sDst[t] = dstG[e0g + t]; sSrc[t] = srcG[e0g + t]; }
        __syncthreads();

        // gather h[src] rows (coalesced 128B each)
        for (int i = t; i < ETILE * CC; i += 512) {
            int e = i >> 5, c = i & 31;
            sHs[i] = g_h[sSrc[e] * CC + c];
        }

        // phase 1: h1 = silu(ee @ Wm1) — thread: 1 edge x 16 outs
        {
            float acc[16];
#pragma unroll
            for (int j = 0; j < 16; j++) acc[j] = 0.f;
#pragma unroll
            for (int b = 0; b < BB; b++) {
                float v = sEE[e2 * BB + b];
#pragma unroll
                for (int j = 0; j < 16; j++) acc[j] += v * sWm1[b * HH + j02 + j];
            }
#pragma unroll
            for (int j = 0; j < 16; j++) sAct[e2 * ACTP + j02 + j] = silu_f(acc[j]);
        }
        __syncthreads();

        // phase 2: h2 = silu(h1 @ Wm2), written transposed sActT[k][e]
        {
            float acc[16];
#pragma unroll
            for (int j = 0; j < 16; j++) acc[j] = 0.f;
#pragma unroll 8
            for (int k = 0; k < HH; k++) {
                float v = sAct[e2 * ACTP + k];
#pragma unroll
                for (int j = 0; j < 16; j++) acc[j] += v * sWm2[k * HH + j02 + j];
            }
#pragma unroll
            for (int j = 0; j < 16; j++)
                sActT[(j02 + j) * TSTR + e2] = silu_f(acc[j]);
        }
        __syncthreads();

        // phase 3: edge-pair FFMA2 GEMM + TP epilogue + scatter
        // thread: 4 edge-pairs (ep = wp + 16i) x 9 outs (o = tx + 32j)
        {
            unsigned long long acc2[4][9];
#pragma unroll
            for (int i = 0; i < 4; i++)
#pragma unroll
                for (int j = 0; j < 9; j++) acc2[i][j] = 0ull;

#pragma unroll 2
            for (int k = 0; k < HH; k++) {
                unsigned long long a2[4];
#pragma unroll
                for (int i = 0; i < 4; i++)
                    a2[i] = lds64(&sActT[k * TSTR + 2 * (wp + 16 * i)]);  // broadcast
#pragma unroll
                for (int j = 0; j < 9; j++) {
                    float b = sWm3[k * WN + tx + 32 * j];
                    unsigned long long bb = pack2(b, b);
#pragma unroll
                    for (int i = 0; i < 4; i++) fma2(acc2[i][j], a2[i], bb);
                }
            }

#pragma unroll
            for (int i = 0; i < 4; i++) {
                int e0 = 2 * (wp + 16 * i);
                int e1 = e0 + 1;
                float* d0 = g_agg + (long long)sDst[e0] * WN;
                float* d1 = g_agg + (long long)sDst[e1] * WN;
                const float* hs0 = &sHs[e0 * CC];
                const float* hs1 = &sHs[e1 * CC];
                const float* sh0 = &sSH[e0 * AA];
                const float* sh1 = &sSH[e1 * AA];
#pragma unroll
                for (int j = 0; j < 9; j++) {
                    int o = tx + 32 * j;
                    float2 w = unpack2(acc2[i][j]);
                    atomicAdd(d0 + o, w.x * hs0[cj[j]] * sh0[aj[j]]);
                    atomicAdd(d1 + o, w.y * hs1[cj[j]] * sh1[aj[j]]);
                }
            }
        }
        __syncthreads();
    }
}

// ---------------------------------------------------------------------------
// out = silu(agg @ W2) + sc_out (R1 scalar version): tile 64x64, micro 4x4
// ---------------------------------------------------------------------------
__global__ void __launch_bounds__(256) k_final(const float* __restrict__ W2,
                                               float* __restrict__ out) {
    __shared__ float sA[32][65];
    __shared__ float sB[32][64];
    int t = threadIdx.x;
    int n0 = blockIdx.x * 64;
    int o0 = blockIdx.y * 64;
    int tr = t >> 4, tc = t & 15;
    float acc[4][4];
#pragma unroll
    for (int i = 0; i < 4; i++)
#pragma unroll
        for (int j = 0; j < 4; j++) acc[i][j] = 0.f;

    for (int kc = 0; kc < WN; kc += 32) {
        for (int i = t; i < 64 * 32; i += 256) {
            int n = i >> 5, kk = i & 31;
            int nn = n0 + n;
            sA[kk][n] = (nn < NN) ? g_agg[(long long)nn * WN + kc + kk] : 0.f;
        }
        for (int i = t; i < 32 * 64; i += 256) {
            int kk = i >> 6, o = i & 63;
            sB[kk][o] = W2[(kc + kk) * FOUT + o0 + o];
        }
        __syncthreads();
#pragma unroll 8
        for (int k = 0; k < 32; k++) {
            float a[4], b[4];
#pragma unroll
            for (int i = 0; i < 4; i++) a[i] = sA[k][tr * 4 + i];
#pragma unroll
            for (int j = 0; j < 4; j++) b[j] = sB[k][tc * 4 + j];
#pragma unroll
            for (int i = 0; i < 4; i++)
#pragma unroll
                for (int j = 0; j < 4; j++) acc[i][j] += a[i] * b[j];
        }
        __syncthreads();
    }
#pragma unroll
    for (int i = 0; i < 4; i++) {
        int nn = n0 + tr * 4 + i;
        if (nn >= NN) continue;
#pragma unroll
        for (int j = 0; j < 4; j++) {
            int o = o0 + tc * 4 + j;
            out[nn * FOUT + o] = silu_f(acc[i][j]) + out[nn * FOUT + o];
        }
    }
}

// ---------------------------------------------------------------------------
extern "C" void kernel_launch(void* const* d_in, const int* in_sizes, int n_in,
                              void* d_out, int out_size) {
    const float* x     = (const float*)d_in[0];
    const float* attrs = (const float*)d_in[1];
    const float* ee    = (const float*)d_in[2];
    const float* sh    = (const float*)d_in[3];
    const int*   eidx  = (const int*)d_in[4];
    const float* W1    = (const float*)d_in[5];
    const float* Wm1   = (const float*)d_in[6];
    const float* Wm2   = (const float*)d_in[7];
    const float* Wm3   = (const float*)d_in[8];
    const float* W2    = (const float*)d_in[9];
    const float* Wsc   = (const float*)d_in[10];
    float* out = (float*)d_out;

    const int* dst = eidx;        // edge_index[0]
    const int* src = eidx + EE;   // edge_index[1]

    k_zero<<<1024, 256>>>();
    k_h<<<NN / 8, 256>>>(x, W1);

    dim3 gsc((NN + 63) / 64, 2);
    k_sc<<<gsc, 256>>>(x, attrs, Wsc, out);

    const int edge_smem =
        (512 + 4096 + 18432 + ETILE * ACTP + HH * TSTR +
         ETILE * BB + ETILE * AA + ETILE * CC) * 4 + 2 * ETILE * 4 + 256;
    cudaFuncSetAttribute(k_edge, cudaFuncAttributeMaxDynamicSharedMemorySize, edge_smem);
    k_edge<<<152, 512, edge_smem>>>(ee, sh, dst, src, Wm1, Wm2, Wm3);

    dim3 gf((NN + 63) / 64, 4);
    k_final<<<gf, 256>>>(W2, out);
}

// round 6
// speedup vs baseline: 1.1637x; 1.0676x over previous
#include <cuda_runtime.h>

#define NN   25000
#define EE   400000
#define FIN  256
#define CC   32
#define AA   9
#define WN   288     // CC*AA
#define BB   8
#define HH   64
#define SSP  4
#define FOUT 256

__device__ float g_h[NN * CC];      // 3.2 MB
__device__ float g_agg[NN * WN];    // 28.8 MB
__device__ int   g_cnt[NN];         // histogram / cursor
__device__ int   g_perm[EE];        // dst-sorted edge permutation

__device__ __forceinline__ float silu_f(float v) {
    return v / (1.0f + __expf(-v));
}

// ---- packed f32x2 helpers ----
__device__ __forceinline__ void fma2(unsigned long long& acc, unsigned long long a,
                                     unsigned long long b) {
    asm("fma.rn.f32x2 %0, %1, %2, %0;" : "+l"(acc) : "l"(a), "l"(b));
}
__device__ __forceinline__ unsigned long long pack2(float x, float y) {
    unsigned long long r;
    asm("mov.b64 %0, {%1, %2};" : "=l"(r) : "f"(x), "f"(y));
    return r;
}
__device__ __forceinline__ float2 unpack2(unsigned long long v) {
    float2 r;
    asm("mov.b64 {%0, %1}, %2;" : "=f"(r.x), "=f"(r.y) : "l"(v));
    return r;
}
__device__ __forceinline__ unsigned long long lds64(const float* p) {
    return *reinterpret_cast<const unsigned long long*>(p);
}

// ---------------------------------------------------------------------------
// zero agg + histogram
// ---------------------------------------------------------------------------
__global__ void k_zero() {
    int i = blockIdx.x * blockDim.x + threadIdx.x;
    int stride = gridDim.x * blockDim.x;
    float4* p = (float4*)g_agg;
    const int n4 = (NN * WN) / 4;
    float4 z = make_float4(0.f, 0.f, 0.f, 0.f);
    for (int k = i; k < n4; k += stride) p[k] = z;
    for (int k = i; k < NN; k += stride) g_cnt[k] = 0;
}

// ---------------------------------------------------------------------------
// counting sort by dst: histogram -> scan -> place
// ---------------------------------------------------------------------------
__global__ void k_hist(const int* __restrict__ dstG) {
    int i = blockIdx.x * blockDim.x + threadIdx.x;
    int stride = gridDim.x * blockDim.x;
    for (int e = i; e < EE; e += stride) atomicAdd(&g_cnt[dstG[e]], 1);
}

__global__ void __launch_bounds__(1024) k_scan() {
    __shared__ int smv[1024];
    const int CH = 25;             // 1024*25 >= 25000
    int t = threadIdx.x;
    int base = t * CH;
    int v[CH];
    int s = 0;
#pragma unroll
    for (int i = 0; i < CH; i++) {
        int idx = base + i;
        v[i] = (idx < NN) ? g_cnt[idx] : 0;
        s += v[i];
    }
    smv[t] = s;
    __syncthreads();
    for (int off = 1; off < 1024; off <<= 1) {
        int x = (t >= off) ? smv[t - off] : 0;
        __syncthreads();
        smv[t] += x;
        __syncthreads();
    }
    int ex = (t > 0) ? smv[t - 1] : 0;
#pragma unroll
    for (int i = 0; i < CH; i++) {
        int idx = base + i;
        if (idx < NN) g_cnt[idx] = ex;   // cursor = segment start
        ex += v[i];
    }
}

__global__ void k_place(const int* __restrict__ dstG) {
    int i = blockIdx.x * blockDim.x + threadIdx.x;
    int stride = gridDim.x * blockDim.x;
    for (int e = i; e < EE; e += stride) {
        int pos = atomicAdd(&g_cnt[dstG[e]], 1);
        g_perm[pos] = e;
    }
}

// ---------------------------------------------------------------------------
// h = 0.25 * (x @ W1)    [NN, CC]
// ---------------------------------------------------------------------------
__global__ void __launch_bounds__(256) k_h(const float* __restrict__ x,
                                           const float* __restrict__ W1) {
    __shared__ float sW1[FIN * CC];
    __shared__ float sX[8][FIN];
    int t = threadIdx.x;
    int n0 = blockIdx.x * 8;
    for (int i = t; i < FIN * CC; i += 256) sW1[i] = W1[i];
    for (int i = t; i < 8 * FIN; i += 256)
        sX[i >> 8][i & 255] = x[(n0 + (i >> 8)) * FIN + (i & 255)];
    __syncthreads();
    int ty = t >> 5, tx = t & 31;
    float acc = 0.f;
#pragma unroll 8
    for (int f = 0; f < FIN; f++) acc += sX[ty][f] * sW1[f * CC + tx];
    g_h[(n0 + ty) * CC + tx] = 0.25f * acc;
}

// ---------------------------------------------------------------------------
// sc_out GEMM (R1 scalar): tile 64x128, micro 4x8
// ---------------------------------------------------------------------------
__global__ void __launch_bounds__(256) k_sc(const float* __restrict__ x,
                                            const float* __restrict__ attrs,
                                            const float* __restrict__ Wsc,
                                            float* __restrict__ out) {
    __shared__ float sA[32][64];
    __shared__ float sB[32][128];
    int t = threadIdx.x;
    int n0 = blockIdx.x * 64;
    int o0 = blockIdx.y * 128;
    int tr = t >> 4;
    int tc = t & 15;
    float acc[4][8];
#pragma unroll
    for (int i = 0; i < 4; i++)
#pragma unroll
        for (int j = 0; j < 8; j++) acc[i][j] = 0.f;

    for (int kc = 0; kc < FIN * SSP; kc += 32) {
        for (int i = t; i < 32 * 64; i += 256) {
            int kk = i >> 6, n = i & 63;
            int k = kc + kk;
            int nn = n0 + n;
            float v = 0.f;
            if (nn < NN) v = x[nn * FIN + (k >> 2)] * attrs[nn * SSP + (k & 3)];
            sA[kk][n] = v;
        }
        for (int i = t; i < 32 * 128; i += 256) {
            int kk = i >> 7, o = i & 127;
            sB[kk][o] = Wsc[(kc + kk) * FOUT + o0 + o];
        }
        __syncthreads();
#pragma unroll 8
        for (int k = 0; k < 32; k++) {
            float a[4], b[8];
#pragma unroll
            for (int i = 0; i < 4; i++) a[i] = sA[k][tr * 4 + i];
#pragma unroll
            for (int j = 0; j < 8; j++) b[j] = sB[k][tc * 8 + j];
#pragma unroll
            for (int i = 0; i < 4; i++)
#pragma unroll
                for (int j = 0; j < 8; j++) acc[i][j] += a[i] * b[j];
        }
        __syncthreads();
    }
#pragma unroll
    for (int i = 0; i < 4; i++) {
        int nn = n0 + tr * 4 + i;
        if (nn >= NN) continue;
#pragma unroll
        for (int j = 0; j < 8; j++)
            out[nn * FOUT + o0 + tc * 8 + j] = acc[i][j];
    }
}

// ---------------------------------------------------------------------------
// fused edge kernel (256 threads, 64-edge tiles, dst-sorted via g_perm)
// ---------------------------------------------------------------------------
#define ACTP 65   // sAct row stride (odd -> conflict-free scalar reads)
#define TSTR 66   // sActT row stride (even -> aligned lds64)

__global__ void __launch_bounds__(256, 1) k_edge(
    const float* __restrict__ eeG, const float* __restrict__ shG,
    const int* __restrict__ dstG, const int* __restrict__ srcG,
    const float* __restrict__ Wm1, const float* __restrict__ Wm2,
    const float* __restrict__ Wm3) {
    extern __shared__ float sm[];
    float* sWm1  = sm;                     // 512
    float* sWm2  = sWm1 + 512;             // 4096
    float* sWm3  = sWm2 + 4096;            // 18432
    float* sAct  = sWm3 + 18432;           // 64*65
    float* sActT = sAct + 64 * ACTP;       // 64*66
    float* sEE   = sActT + 64 * TSTR;      // 512
    float* sSH   = sEE + 512;              // 576
    float* sHs   = sSH + 576;              // 2048
    int*   sDst  = (int*)(sHs + 2048);     // 64
    int*   sSrc  = sDst + 64;              // 64
    int*   sEid  = sSrc + 64;              // 64

    int t = threadIdx.x;
    for (int i = t; i < 512;   i += 256) sWm1[i] = Wm1[i];
    for (int i = t; i < 4096;  i += 256) sWm2[i] = Wm2[i];
    for (int i = t; i < 18432; i += 256) sWm3[i] = Wm3[i];
    __syncthreads();

    const int tx = t & 31, ty = t >> 5;    // warp ty owns edges 8ty..8ty+7
    const int e_loc = t & 63;
    const int j0 = (t >> 6) * 16;

    int cj[9], aj[9];
#pragma unroll
    for (int j = 0; j < 9; j++) {
        int o = tx + 32 * j;
        cj[j] = o / 9;
        aj[j] = o - 9 * cj[j];
    }

    for (int tile = blockIdx.x; tile < EE / 64; tile += gridDim.x) {
        int e0g = tile * 64;
        if (t < 64) {
            int eg = g_perm[e0g + t];
            sEid[t] = eg;
            sDst[t] = dstG[eg];
            sSrc[t] = srcG[eg];
        }
        __syncthreads();
        for (int i = t; i < 64 * BB; i += 256) {
            int e = i >> 3, b = i & 7;
            sEE[i] = eeG[sEid[e] * BB + b];
        }
        for (int i = t; i < 64 * AA; i += 256) {
            int e = i / AA, a = i - AA * e;
            sSH[i] = shG[sEid[e] * AA + a];
        }
        for (int i = t; i < 64 * CC; i += 256) {
            int e = i >> 5, c = i & 31;
            sHs[i] = g_h[sSrc[e] * CC + c];
        }
        __syncthreads();

        // phase 1: h1 = silu(ee @ Wm1)
        {
            float acc[16];
#pragma unroll
            for (int j = 0; j < 16; j++) acc[j] = 0.f;
#pragma unroll
            for (int b = 0; b < BB; b++) {
                float v = sEE[e_loc * BB + b];
#pragma unroll
                for (int j = 0; j < 16; j++) acc[j] += v * sWm1[b * HH + j0 + j];
            }
#pragma unroll
            for (int j = 0; j < 16; j++) sAct[e_loc * ACTP + j0 + j] = silu_f(acc[j]);
        }
        __syncthreads();

        // phase 2: h2 = silu(h1 @ Wm2), written transposed sActT[k][e]
        {
            float acc[16];
#pragma unroll
            for (int j = 0; j < 16; j++) acc[j] = 0.f;
#pragma unroll 8
            for (int k = 0; k < HH; k++) {
                float v = sAct[e_loc * ACTP + k];
#pragma unroll
                for (int j = 0; j < 16; j++) acc[j] += v * sWm2[k * HH + j0 + j];
            }
#pragma unroll
            for (int j = 0; j < 16; j++)
                sActT[(j0 + j) * TSTR + e_loc] = silu_f(acc[j]);
        }
        __syncthreads();

        // phase 3: edge-pair FFMA2 GEMM; warp ty owns edges 8ty..8ty+7
        {
            unsigned long long acc2[4][9];
#pragma unroll
            for (int m = 0; m < 4; m++)
#pragma unroll
                for (int j = 0; j < 9; j++) acc2[m][j] = 0ull;

#pragma unroll 2
            for (int k = 0; k < HH; k++) {
                unsigned long long a2[4];
#pragma unroll
                for (int m = 0; m < 4; m++)
                    a2[m] = lds64(&sActT[k * TSTR + 8 * ty + 2 * m]);  // broadcast
#pragma unroll
                for (int j = 0; j < 9; j++) {
                    float b = sWm3[k * WN + tx + 32 * j];
                    unsigned long long bb = pack2(b, b);
#pragma unroll
                    for (int m = 0; m < 4; m++) fma2(acc2[m][j], a2[m], bb);
                }
            }

            // epilogue: run-length reduce over consecutive sorted edges, then atomics
            float racc[9];
#pragma unroll
            for (int j = 0; j < 9; j++) racc[j] = 0.f;
            int cur = sDst[8 * ty];

#pragma unroll
            for (int m = 0; m < 4; m++) {
                int e0 = 8 * ty + 2 * m;
                int e1 = e0 + 1;
                const float* hs0 = &sHs[e0 * CC];
                const float* hs1 = &sHs[e1 * CC];
                const float* sh0 = &sSH[e0 * AA];
                const float* sh1 = &sSH[e1 * AA];
                int d0 = sDst[e0], d1 = sDst[e1];
                if (d0 != cur) {
                    float* dp = g_agg + (long long)cur * WN;
#pragma unroll
                    for (int j = 0; j < 9; j++) {
                        atomicAdd(dp + tx + 32 * j, racc[j]);
                        racc[j] = 0.f;
                    }
                    cur = d0;
                }
#pragma unroll
                for (int j = 0; j < 9; j++) {
                    float2 w = unpack2(acc2[m][j]);
                    racc[j] += w.x * hs0[cj[j]] * sh0[aj[j]];
                }
                if (d1 != cur) {
                    float* dp = g_agg + (long long)cur * WN;
#pragma unroll
                    for (int j = 0; j < 9; j++) {
                        atomicAdd(dp + tx + 32 * j, racc[j]);
                        racc[j] = 0.f;
                    }
                    cur = d1;
                }
#pragma unroll
                for (int j = 0; j < 9; j++) {
                    float2 w = unpack2(acc2[m][j]);
                    racc[j] += w.y * hs1[cj[j]] * sh1[aj[j]];
                }
            }
            {
                float* dp = g_agg + (long long)cur * WN;
#pragma unroll
                for (int j = 0; j < 9; j++) atomicAdd(dp + tx + 32 * j, racc[j]);
            }
        }
        __syncthreads();
    }
}

// ---------------------------------------------------------------------------
// out = silu(agg @ W2) + sc_out (R1 scalar): tile 64x64, micro 4x4
// ---------------------------------------------------------------------------
__global__ void __launch_bounds__(256) k_final(const float* __restrict__ W2,
                                               float* __restrict__ out) {
    __shared__ float sA[32][65];
    __shared__ float sB[32][64];
    int t = threadIdx.x;
    int n0 = blockIdx.x * 64;
    int o0 = blockIdx.y * 64;
    int tr = t >> 4, tc = t & 15;
    float acc[4][4];
#pragma unroll
    for (int i = 0; i < 4; i++)
#pragma unroll
        for (int j = 0; j < 4; j++) acc[i][j] = 0.f;

    for (int kc = 0; kc < WN; kc += 32) {
        for (int i = t; i < 64 * 32; i += 256) {
            int n = i >> 5, kk = i & 31;
            int nn = n0 + n;
            sA[kk][n] = (nn < NN) ? g_agg[(long long)nn * WN + kc + kk] : 0.f;
        }
        for (int i = t; i < 32 * 64; i += 256) {
            int kk = i >> 6, o = i & 63;
            sB[kk][o] = W2[(kc + kk) * FOUT + o0 + o];
        }
        __syncthreads();
#pragma unroll 8
        for (int k = 0; k < 32; k++) {
            float a[4], b[4];
#pragma unroll
            for (int i = 0; i < 4; i++) a[i] = sA[k][tr * 4 + i];
#pragma unroll
            for (int j = 0; j < 4; j++) b[j] = sB[k][tc * 4 + j];
#pragma unroll
            for (int i = 0; i < 4; i++)
#pragma unroll
                for (int j = 0; j < 4; j++) acc[i][j] += a[i] * b[j];
        }
        __syncthreads();
    }
#pragma unroll
    for (int i = 0; i < 4; i++) {
        int nn = n0 + tr * 4 + i;
        if (nn >= NN) continue;
#pragma unroll
        for (int j = 0; j < 4; j++) {
            int o = o0 + tc * 4 + j;
            out[nn * FOUT + o] = silu_f(acc[i][j]) + out[nn * FOUT + o];
        }
    }
}

// ---------------------------------------------------------------------------
extern "C" void kernel_launch(void* const* d_in, const int* in_sizes, int n_in,
                              void* d_out, int out_size) {
    const float* x     = (const float*)d_in[0];
    const float* attrs = (const float*)d_in[1];
    const float* ee    = (const float*)d_in[2];
    const float* sh    = (const float*)d_in[3];
    const int*   eidx  = (const int*)d_in[4];
    const float* W1    = (const float*)d_in[5];
    const float* Wm1   = (const float*)d_in[6];
    const float* Wm2   = (const float*)d_in[7];
    const float* Wm3   = (const float*)d_in[8];
    const float* W2    = (const float*)d_in[9];
    const float* Wsc   = (const float*)d_in[10];
    float* out = (float*)d_out;

    const int* dst = eidx;        // edge_index[0]
    const int* src = eidx + EE;   // edge_index[1]

    k_zero<<<1024, 256>>>();
    k_hist<<<400, 256>>>(dst);
    k_scan<<<1, 1024>>>();
    k_place<<<400, 256>>>(dst);

    k_h<<<NN / 8, 256>>>(x, W1);

    dim3 gsc((NN + 63) / 64, 2);
    k_sc<<<gsc, 256>>>(x, attrs, Wsc, out);

    const int edge_smem =
        (512 + 4096 + 18432 + 64 * ACTP + 64 * TSTR + 512 + 576 + 2048) * 4 +
        3 * 64 * 4 + 256;
    cudaFuncSetAttribute(k_edge, cudaFuncAttributeMaxDynamicSharedMemorySize, edge_smem);
    k_edge<<<152, 256, edge_smem>>>(ee, sh, dst, src, Wm1, Wm2, Wm3);

    dim3 gf((NN + 63) / 64, 4);
    k_final<<<gf, 256>>>(W2, out);
}

// round 8
// speedup vs baseline: 1.3994x; 1.2026x over previous
#include <cuda_runtime.h>
#include <cuda_bf16.h>
#include <mma.h>
#include <cstdint>

using namespace nvcuda;

#define NN   25000
#define EE   400000
#define FIN  256
#define CC   32
#define AA   9
#define WN   288     // CC*AA
#define BB   8
#define HH   64
#define SSP  4
#define FOUT 256

__device__ float g_h[NN * CC];      // 3.2 MB
__device__ float g_agg[NN * WN];    // 28.8 MB
__device__ int   g_cnt[NN];
__device__ int   g_perm[EE];
// pre-split Wsc for tensor k_sc: [1024][256] bf16 hi/lo, row-major (k, o)
__device__ __nv_bfloat16 g_Bhi[1024 * 256];
__device__ __nv_bfloat16 g_Blo[1024 * 256];

__device__ __forceinline__ float silu_f(float v) {
    return v / (1.0f + __expf(-v));
}

// ---- packed f32x2 helpers ----
__device__ __forceinline__ void fma2(unsigned long long& acc, unsigned long long a,
                                     unsigned long long b) {
    asm("fma.rn.f32x2 %0, %1, %2, %0;" : "+l"(acc) : "l"(a), "l"(b));
}
__device__ __forceinline__ unsigned long long pack2(float x, float y) {
    unsigned long long r;
    asm("mov.b64 %0, {%1, %2};" : "=l"(r) : "f"(x), "f"(y));
    return r;
}
__device__ __forceinline__ float2 unpack2(unsigned long long v) {
    float2 r;
    asm("mov.b64 {%0, %1}, %2;" : "=f"(r.x), "=f"(r.y) : "l"(v));
    return r;
}
__device__ __forceinline__ unsigned long long lds64(const float* p) {
    return *reinterpret_cast<const unsigned long long*>(p);
}

// ---------------------------------------------------------------------------
__global__ void k_zero() {
    int i = blockIdx.x * blockDim.x + threadIdx.x;
    int stride = gridDim.x * blockDim.x;
    float4* p = (float4*)g_agg;
    const int n4 = (NN * WN) / 4;
    float4 z = make_float4(0.f, 0.f, 0.f, 0.f);
    for (int k = i; k < n4; k += stride) p[k] = z;
    for (int k = i; k < NN; k += stride) g_cnt[k] = 0;
}

// ---------------------------------------------------------------------------
// counting sort by dst
// ---------------------------------------------------------------------------
__global__ void k_hist(const int* __restrict__ dstG) {
    int i = blockIdx.x * blockDim.x + threadIdx.x;
    int stride = gridDim.x * blockDim.x;
    for (int e = i; e < EE; e += stride) atomicAdd(&g_cnt[dstG[e]], 1);
}

__global__ void __launch_bounds__(1024) k_scan() {
    __shared__ int smv[1024];
    const int CH = 25;
    int t = threadIdx.x;
    int base = t * CH;
    int v[CH];
    int s = 0;
#pragma unroll
    for (int i = 0; i < CH; i++) {
        int idx = base + i;
        v[i] = (idx < NN) ? g_cnt[idx] : 0;
        s += v[i];
    }
    smv[t] = s;
    __syncthreads();
    for (int off = 1; off < 1024; off <<= 1) {
        int x = (t >= off) ? smv[t - off] : 0;
        __syncthreads();
        smv[t] += x;
        __syncthreads();
    }
    int ex = (t > 0) ? smv[t - 1] : 0;
#pragma unroll
    for (int i = 0; i < CH; i++) {
        int idx = base + i;
        if (idx < NN) g_cnt[idx] = ex;
        ex += v[i];
    }
}

__global__ void k_place(const int* __restrict__ dstG) {
    int i = blockIdx.x * blockDim.x + threadIdx.x;
    int stride = gridDim.x * blockDim.x;
    for (int e = i; e < EE; e += stride) {
        int pos = atomicAdd(&g_cnt[dstG[e]], 1);
        g_perm[pos] = e;
    }
}

// ---------------------------------------------------------------------------
// h = 0.25 * (x @ W1)    [NN, CC]
// ---------------------------------------------------------------------------
__global__ void __launch_bounds__(256) k_h(const float* __restrict__ x,
                                           const float* __restrict__ W1) {
    __shared__ float sW1[FIN * CC];
    __shared__ float sX[8][FIN];
    int t = threadIdx.x;
    int n0 = blockIdx.x * 8;
    for (int i = t; i < FIN * CC; i += 256) sW1[i] = W1[i];
    for (int i = t; i < 8 * FIN; i += 256)
        sX[i >> 8][i & 255] = x[(n0 + (i >> 8)) * FIN + (i & 255)];
    __syncthreads();
    int ty = t >> 5, tx = t & 31;
    float acc = 0.f;
#pragma unroll 8
    for (int f = 0; f < FIN; f++) acc += sX[ty][f] * sW1[f * CC + tx];
    g_h[(n0 + ty) * CC + tx] = 0.25f * acc;
}

// ---------------------------------------------------------------------------
// split Wsc (fp32 [1024][256]) into bf16 hi/lo, row-major
// ---------------------------------------------------------------------------
__global__ void k_bsplit(const float* __restrict__ Wsc) {
    int idx = blockIdx.x * blockDim.x + threadIdx.x;
    if (idx >= 1024 * 256) return;
    float v = Wsc[idx];
    __nv_bfloat16 hi = __float2bfloat16(v);
    __nv_bfloat16 lo = __float2bfloat16(v - __bfloat162float(hi));
    g_Bhi[idx] = hi;
    g_Blo[idx] = lo;
}

// ---------------------------------------------------------------------------
// tensor-core (wmma/HMMA) k_sc: out[n,o] = sum_k xa[n,k]*Wsc[k,o]
// bf16 split: D = Ahi*Bhi + Ahi*Blo + Alo*Bhi
// CTA: 64 nodes x 256 outs, 8 warps (2 x 4), warp tile 32x64
// ---------------------------------------------------------------------------
#define ASTR 40    // A smem row stride (bf16 elements)
#define BSTR 264   // B smem row stride (bf16 elements)

__global__ void __launch_bounds__(256) k_sc_mm(const float* __restrict__ x,
                                               const float* __restrict__ attrs,
                                               float* __restrict__ out) {
    extern __shared__ char smem[];
    __nv_bfloat16* sAhi = (__nv_bfloat16*)smem;                        // 64*40
    __nv_bfloat16* sAlo = sAhi + 64 * ASTR;                            // 64*40
    __nv_bfloat16* sBhi = sAlo + 64 * ASTR;                            // 32*264
    __nv_bfloat16* sBlo = sBhi + 32 * BSTR;                            // 32*264
    float* sOut = (float*)smem;  // epilogue reuse: 32*264 floats

    int t = threadIdx.x;
    int wid = t >> 5;
    int warp_m = wid >> 2;       // 0..1
    int warp_n = wid & 3;        // 0..3
    int n0 = blockIdx.x * 64;

    wmma::fragment<wmma::accumulator, 16, 16, 16, float> acc[2][4];
#pragma unroll
    for (int im = 0; im < 2; im++)
#pragma unroll
        for (int jn = 0; jn < 4; jn++) wmma::fill_fragment(acc[im][jn], 0.0f);

    for (int kc = 0; kc < FIN * SSP; kc += 32) {
        // stage A: xa[n,k] = x[n,k>>2]*attrs[n,k&3], split hi/lo
        for (int i = t; i < 64 * 32; i += 256) {
            int n = i >> 5, kk = i & 31;
            int k = kc + kk;
            int nn = n0 + n;
            float a = 0.f;
            if (nn < NN) a = x[nn * FIN + (k >> 2)] * attrs[nn * SSP + (k & 3)];
            __nv_bfloat16 hi = __float2bfloat16(a);
            __nv_bfloat16 lo = __float2bfloat16(a - __bfloat162float(hi));
            sAhi[n * ASTR + kk] = hi;
            sAlo[n * ASTR + kk] = lo;
        }
        // stage B: rows kc..kc+31 of pre-split Wsc
        for (int i = t; i < 32 * 256; i += 256) {
            int r = i >> 8, c = i & 255;
            sBhi[r * BSTR + c] = g_Bhi[(kc + r) * 256 + c];
            sBlo[r * BSTR + c] = g_Blo[(kc + r) * 256 + c];
        }
        __syncthreads();

#pragma unroll
        for (int kf = 0; kf < 2; kf++) {
            wmma::fragment<wmma::matrix_a, 16, 16, 16, __nv_bfloat16,
                           wmma::row_major> ahi[2], alo[2];
#pragma unroll
            for (int im = 0; im < 2; im++) {
                const __nv_bfloat16* ap =
                    sAhi + (warp_m * 32 + 16 * im) * ASTR + kf * 16;
                const __nv_bfloat16* alp =
                    sAlo + (warp_m * 32 + 16 * im) * ASTR + kf * 16;
                wmma::load_matrix_sync(ahi[im], ap, ASTR);
                wmma::load_matrix_sync(alo[im], alp, ASTR);
            }
#pragma unroll
            for (int jn = 0; jn < 4; jn++) {
                wmma::fragment<wmma::matrix_b, 16, 16, 16, __nv_bfloat16,
                               wmma::row_major> bhi, blo;
                const __nv_bfloat16* bp =
                    sBhi + (kf * 16) * BSTR + warp_n * 64 + 16 * jn;
                const __nv_bfloat16* blp =
                    sBlo + (kf * 16) * BSTR + warp_n * 64 + 16 * jn;
                wmma::load_matrix_sync(bhi, bp, BSTR);
                wmma::load_matrix_sync(blo, blp, BSTR);
#pragma unroll
                for (int im = 0; im < 2; im++) {
                    wmma::mma_sync(acc[im][jn], ahi[im], bhi, acc[im][jn]);
                    wmma::mma_sync(acc[im][jn], ahi[im], blo, acc[im][jn]);
                    wmma::mma_sync(acc[im][jn], alo[im], bhi, acc[im][jn]);
                }
            }
        }
        __syncthreads();
    }

    // epilogue: two 32-row passes through smem with bounds guard
    for (int half = 0; half < 2; half++) {
        if (warp_m == half) {
#pragma unroll
            for (int im = 0; im < 2; im++)
#pragma unroll
                for (int jn = 0; jn < 4; jn++)
                    wmma::store_matrix_sync(
                        sOut + (16 * im) * BSTR + warp_n * 64 + 16 * jn,
                        acc[im][jn], BSTR, wmma::mem_row_major);
        }
        __syncthreads();
        for (int i = t; i < 32 * 256; i += 256) {
            int r = i >> 8, c = i & 255;
            int nn = n0 + half * 32 + r;
            if (nn < NN) out[(long long)nn * FOUT + c] = sOut[r * BSTR + c];
        }
        __syncthreads();
    }
}

// ---------------------------------------------------------------------------
// fused edge kernel (R6: 256 threads, 64-edge tiles, dst-sorted)
// ---------------------------------------------------------------------------
#define ACTP 65
#define TSTR 66

__global__ void __launch_bounds__(256, 1) k_edge(
    const float* __restrict__ eeG, const float* __restrict__ shG,
    const int* __restrict__ dstG, const int* __restrict__ srcG,
    const float* __restrict__ Wm1, const float* __restrict__ Wm2,
    const float* __restrict__ Wm3) {
    extern __shared__ float sm[];
    float* sWm1  = sm;
    float* sWm2  = sWm1 + 512;
    float* sWm3  = sWm2 + 4096;
    float* sAct  = sWm3 + 18432;
    float* sActT = sAct + 64 * ACTP;
    float* sEE   = sActT + 64 * TSTR;
    float* sSH   = sEE + 512;
    float* sHs   = sSH + 576;
    int*   sDst  = (int*)(sHs + 2048);
    int*   sSrc  = sDst + 64;
    int*   sEid  = sSrc + 64;

    int t = threadIdx.x;
    for (int i = t; i < 512;   i += 256) sWm1[i] = Wm1[i];
    for (int i = t; i < 4096;  i += 256) sWm2[i] = Wm2[i];
    for (int i = t; i < 18432; i += 256) sWm3[i] = Wm3[i];
    __syncthreads();

    const int tx = t & 31, ty = t >> 5;
    const int e_loc = t & 63;
    const int j0 = (t >> 6) * 16;

    int cj[9], aj[9];
#pragma unroll
    for (int j = 0; j < 9; j++) {
        int o = tx + 32 * j;
        cj[j] = o / 9;
        aj[j] = o - 9 * cj[j];
    }

    for (int tile = blockIdx.x; tile < EE / 64; tile += gridDim.x) {
        int e0g = tile * 64;
        if (t < 64) {
            int eg = g_perm[e0g + t];
            sEid[t] = eg;
            sDst[t] = dstG[eg];
            sSrc[t] = srcG[eg];
        }
        __syncthreads();
        for (int i = t; i < 64 * BB; i += 256) {
            int e = i >> 3, b = i & 7;
            sEE[i] = eeG[sEid[e] * BB + b];
        }
        for (int i = t; i < 64 * AA; i += 256) {
            int e = i / AA, a = i - AA * e;
            sSH[i] = shG[sEid[e] * AA + a];
        }
        for (int i = t; i < 64 * CC; i += 256) {
            int e = i >> 5, c = i & 31;
            sHs[i] = g_h[sSrc[e] * CC + c];
        }
        __syncthreads();

        // phase 1
        {
            float acc[16];
#pragma unroll
            for (int j = 0; j < 16; j++) acc[j] = 0.f;
#pragma unroll
            for (int b = 0; b < BB; b++) {
                float v = sEE[e_loc * BB + b];
#pragma unroll
                for (int j = 0; j < 16; j++) acc[j] += v * sWm1[b * HH + j0 + j];
            }
#pragma unroll
            for (int j = 0; j < 16; j++) sAct[e_loc * ACTP + j0 + j] = silu_f(acc[j]);
        }
        __syncthreads();

        // phase 2 (transposed output)
        {
            float acc[16];
#pragma unroll
            for (int j = 0; j < 16; j++) acc[j] = 0.f;
#pragma unroll 8
            for (int k = 0; k < HH; k++) {
                float v = sAct[e_loc * ACTP + k];
#pragma unroll
                for (int j = 0; j < 16; j++) acc[j] += v * sWm2[k * HH + j0 + j];
            }
#pragma unroll
            for (int j = 0; j < 16; j++)
                sActT[(j0 + j) * TSTR + e_loc] = silu_f(acc[j]);
        }
        __syncthreads();

        // phase 3: edge-pair FFMA2 + run-length scatter
        {
            unsigned long long acc2[4][9];
#pragma unroll
            for (int m = 0; m < 4; m++)
#pragma unroll
                for (int j = 0; j < 9; j++) acc2[m][j] = 0ull;

#pragma unroll 2
            for (int k = 0; k < HH; k++) {
                unsigned long long a2[4];
#pragma unroll
                for (int m = 0; m < 4; m++)
                    a2[m] = lds64(&sActT[k * TSTR + 8 * ty + 2 * m]);
#pragma unroll
                for (int j = 0; j < 9; j++) {
                    float b = sWm3[k * WN + tx + 32 * j];
                    unsigned long long bb = pack2(b, b);
#pragma unroll
                    for (int m = 0; m < 4; m++) fma2(acc2[m][j], a2[m], bb);
                }
            }

            float racc[9];
#pragma unroll
            for (int j = 0; j < 9; j++) racc[j] = 0.f;
            int cur = sDst[8 * ty];

#pragma unroll
            for (int m = 0; m < 4; m++) {
                int e0 = 8 * ty + 2 * m;
                int e1 = e0 + 1;
                const float* hs0 = &sHs[e0 * CC];
                const float* hs1 = &sHs[e1 * CC];
                const float* sh0 = &sSH[e0 * AA];
                const float* sh1 = &sSH[e1 * AA];
                int d0 = sDst[e0], d1 = sDst[e1];
                if (d0 != cur) {
                    float* dp = g_agg + (long long)cur * WN;
#pragma unroll
                    for (int j = 0; j < 9; j++) {
                        atomicAdd(dp + tx + 32 * j, racc[j]);
                        racc[j] = 0.f;
                    }
                    cur = d0;
                }
#pragma unroll
                for (int j = 0; j < 9; j++) {
                    float2 w = unpack2(acc2[m][j]);
                    racc[j] += w.x * hs0[cj[j]] * sh0[aj[j]];
                }
                if (d1 != cur) {
                    float* dp = g_agg + (long long)cur * WN;
#pragma unroll
                    for (int j = 0; j < 9; j++) {
                        atomicAdd(dp + tx + 32 * j, racc[j]);
                        racc[j] = 0.f;
                    }
                    cur = d1;
                }
#pragma unroll
                for (int j = 0; j < 9; j++) {
                    float2 w = unpack2(acc2[m][j]);
                    racc[j] += w.y * hs1[cj[j]] * sh1[aj[j]];
                }
            }
            {
                float* dp = g_agg + (long long)cur * WN;
#pragma unroll
                for (int j = 0; j < 9; j++) atomicAdd(dp + tx + 32 * j, racc[j]);
            }
        }
        __syncthreads();
    }
}

// ---------------------------------------------------------------------------
// out = silu(agg @ W2) + sc_out (R1 scalar)
// ---------------------------------------------------------------------------
__global__ void __launch_bounds__(256) k_final(const float* __restrict__ W2,
                                               float* __restrict__ out) {
    __shared__ float sA[32][65];
    __shared__ float sB[32][64];
    int t = threadIdx.x;
    int n0 = blockIdx.x * 64;
    int o0 = blockIdx.y * 64;
    int tr = t >> 4, tc = t & 15;
    float acc[4][4];
#pragma unroll
    for (int i = 0; i < 4; i++)
#pragma unroll
        for (int j = 0; j < 4; j++) acc[i][j] = 0.f;

    for (int kc = 0; kc < WN; kc += 32) {
        for (int i = t; i < 64 * 32; i += 256) {
            int n = i >> 5, kk = i & 31;
            int nn = n0 + n;
            sA[kk][n] = (nn < NN) ? g_agg[(long long)nn * WN + kc + kk] : 0.f;
        }
        for (int i = t; i < 32 * 64; i += 256) {
            int kk = i >> 6, o = i & 63;
            sB[kk][o] = W2[(kc + kk) * FOUT + o0 + o];
        }
        __syncthreads();
#pragma unroll 8
        for (int k = 0; k < 32; k++) {
            float a[4], b[4];
#pragma unroll
            for (int i = 0; i < 4; i++) a[i] = sA[k][tr * 4 + i];
#pragma unroll
            for (int j = 0; j < 4; j++) b[j] = sB[k][tc * 4 + j];
#pragma unroll
            for (int i = 0; i < 4; i++)
#pragma unroll
                for (int j = 0; j < 4; j++) acc[i][j] += a[i] * b[j];
        }
        __syncthreads();
    }
#pragma unroll
    for (int i = 0; i < 4; i++) {
        int nn = n0 + tr * 4 + i;
        if (nn >= NN) continue;
#pragma unroll
        for (int j = 0; j < 4; j++) {
            int o = o0 + tc * 4 + j;
            out[nn * FOUT + o] = silu_f(acc[i][j]) + out[nn * FOUT + o];
        }
    }
}

// ---------------------------------------------------------------------------
extern "C" void kernel_launch(void* const* d_in, const int* in_sizes, int n_in,
                              void* d_out, int out_size) {
    const float* x     = (const float*)d_in[0];
    const float* attrs = (const float*)d_in[1];
    const float* ee    = (const float*)d_in[2];
    const float* sh    = (const float*)d_in[3];
    const int*   eidx  = (const int*)d_in[4];
    const float* W1    = (const float*)d_in[5];
    const float* Wm1   = (const float*)d_in[6];
    const float* Wm2   = (const float*)d_in[7];
    const float* Wm3   = (const float*)d_in[8];
    const float* W2    = (const float*)d_in[9];
    const float* Wsc   = (const float*)d_in[10];
    float* out = (float*)d_out;

    const int* dst = eidx;
    const int* src = eidx + EE;

    k_zero<<<1024, 256>>>();
    k_hist<<<400, 256>>>(dst);
    k_scan<<<1, 1024>>>();
    k_place<<<400, 256>>>(dst);

    k_h<<<NN / 8, 256>>>(x, W1);
    k_bsplit<<<1024, 256>>>(Wsc);

    const int sc_smem = (2 * 64 * ASTR + 2 * 32 * BSTR) * 2 + 256;
    cudaFuncSetAttribute(k_sc_mm, cudaFuncAttributeMaxDynamicSharedMemorySize, sc_smem);
    k_sc_mm<<<(NN + 63) / 64, 256, sc_smem>>>(x, attrs, out);

    const int edge_smem =
        (512 + 4096 + 18432 + 64 * ACTP + 64 * TSTR + 512 + 576 + 2048) * 4 +
        3 * 64 * 4 + 256;
    cudaFuncSetAttribute(k_edge, cudaFuncAttributeMaxDynamicSharedMemorySize, edge_smem);
    k_edge<<<152, 256, edge_smem>>>(ee, sh, dst, src, Wm1, Wm2, Wm3);

    dim3 gf((NN + 63) / 64, 4);
    k_final<<<gf, 256>>>(W2, out);
}